// round 3
// baseline (speedup 1.0000x reference)
#include <cuda_runtime.h>
#include <math.h>

#define G_   4
#define CG   16
#define H_   64
#define W_   64
#define HW   4096
#define COUT 64
#define N_   32

typedef unsigned long long u64;

// Scratch (static device globals; no runtime allocation)
__device__ float g_xt [N_ * G_ * HW * CG];   // x transposed: [n][g][p][c] (c contiguous)
__device__ float g_pre[N_ * COUT * HW];      // pre-norm conv output (b_dc cancels)
__device__ float g_sum[N_ * COUT];
__device__ float g_sq [N_ * COUT];

// ---- packed f32x2 helpers (Blackwell) ----
__device__ __forceinline__ u64 pack2(float lo, float hi) {
    u64 r; asm("mov.b64 %0,{%1,%2};" : "=l"(r) : "f"(lo), "f"(hi)); return r;
}
__device__ __forceinline__ float2 unpack2(u64 v) {
    float2 r; asm("mov.b64 {%0,%1},%2;" : "=f"(r.x), "=f"(r.y) : "l"(v)); return r;
}
__device__ __forceinline__ void ffma2(u64 &d, u64 a, u64 b) {
    asm("fma.rn.f32x2 %0,%1,%2,%0;" : "+l"(d) : "l"(a), "l"(b));
}
__device__ __forceinline__ u64 dup2(float v) { return pack2(v, v); }

__global__ void zero_stats_kernel() {
    int i = blockIdx.x * blockDim.x + threadIdx.x;
    if (i < N_ * COUT) { g_sum[i] = 0.f; g_sq[i] = 0.f; }
}

// x[n][c][p] -> x_t[n][g][p][cg]
__global__ void transpose_kernel(const float* __restrict__ x) {
    const int p = blockIdx.x * 256 + threadIdx.x;
    const int g = blockIdx.y, n = blockIdx.z;
    const float* xs = x + ((size_t)(n * 64 + g * 16)) * HW + p;
    float v[16];
    #pragma unroll
    for (int c = 0; c < 16; c++) v[c] = __ldg(xs + (size_t)c * HW);
    float4* dst = reinterpret_cast<float4*>(g_xt + (((size_t)(n * 4 + g)) * HW + p) * 16);
    dst[0] = make_float4(v[0],  v[1],  v[2],  v[3]);
    dst[1] = make_float4(v[4],  v[5],  v[6],  v[7]);
    dst[2] = make_float4(v[8],  v[9],  v[10], v[11]);
    dst[3] = make_float4(v[12], v[13], v[14], v[15]);
}

// Fused: offset conv (in-register) + deformable bilinear sampling + grouped
// einsum + per-(n,channel) sum/sumsq stats. One pixel per thread.
// Weights in smem arranged for LDS.128 (ulonglong2) consumption.
__global__ __launch_bounds__(128) void fused_kernel(const float* __restrict__ w_off,
                                                    const float* __restrict__ b_off,
                                                    const float* __restrict__ w_dc) {
    // conv weights: swc[pos][c][k10]  k padded 9->10 (pad=0), pairs over (dy,dx)
    __shared__ __align__(16) u64 swc[9 * 16 * 10];
    // einsum weights: swe[k][c][op]   pairs over output channels
    __shared__ __align__(16) u64 swe[9 * 16 * 8];
    __shared__ u64 sb[9];
    __shared__ float s_sum[16], s_sq[16];

    const int tid = threadIdx.x;
    const int g = blockIdx.y, n = blockIdx.z;

    for (int i = tid; i < 9 * 16 * 10; i += 128) {
        const int pos = i / 160, c = (i / 10) % 16, k = i % 10;
        u64 v = 0ULL;
        if (k < 9) {
            const float lo = w_off[((g * 18 + 2 * k)     * 16 + c) * 9 + pos];
            const float hi = w_off[((g * 18 + 2 * k + 1) * 16 + c) * 9 + pos];
            v = pack2(lo, hi);
        }
        swc[i] = v;
    }
    for (int i = tid; i < 9 * 16 * 8; i += 128) {
        const int k = i / 128, c = (i / 8) % 16, op = i % 8;
        const float lo = w_dc[((g * 16 + 2 * op)     * 16 + c) * 9 + k];
        const float hi = w_dc[((g * 16 + 2 * op + 1) * 16 + c) * 9 + k];
        swe[i] = pack2(lo, hi);
    }
    if (tid < 9)  sb[tid] = pack2(b_off[g * 18 + 2 * tid], b_off[g * 18 + 2 * tid + 1]);
    if (tid < 16) { s_sum[tid] = 0.f; s_sq[tid] = 0.f; }
    __syncthreads();

    const int p = blockIdx.x * 128 + tid;
    const int h = p >> 6, w = p & 63;
    const float* xtg = g_xt + ((size_t)(n * 4 + g)) * HW * 16;

    // ---- Phase A: 18 offsets (9 packed (dy,dx) pairs) via grouped 3x3 conv ----
    u64 accoff[10];
    #pragma unroll
    for (int k = 0; k < 9; k++) accoff[k] = sb[k];
    accoff[9] = 0ULL;   // pad sink

    #pragma unroll 1
    for (int pos = 0; pos < 9; pos++) {
        const int y  = h + pos / 3 - 1;
        const int xx = w + pos % 3 - 1;
        if (y < 0 || y >= H_ || xx < 0 || xx >= W_) continue;
        const float4* xp = reinterpret_cast<const float4*>(xtg + (y * 64 + xx) * 16);
        const ulonglong2* wp = reinterpret_cast<const ulonglong2*>(&swc[pos * 160]);
        #pragma unroll
        for (int j = 0; j < 4; j++) {
            const float4 X = xp[j];
            const float xv[4] = {X.x, X.y, X.z, X.w};
            #pragma unroll
            for (int q = 0; q < 4; q++) {
                const int c = 4 * j + q;
                const u64 xd = dup2(xv[q]);
                const ulonglong2 w0 = wp[c * 5 + 0];
                const ulonglong2 w1 = wp[c * 5 + 1];
                const ulonglong2 w2 = wp[c * 5 + 2];
                const ulonglong2 w3 = wp[c * 5 + 3];
                const ulonglong2 w4 = wp[c * 5 + 4];
                ffma2(accoff[0], w0.x, xd); ffma2(accoff[1], w0.y, xd);
                ffma2(accoff[2], w1.x, xd); ffma2(accoff[3], w1.y, xd);
                ffma2(accoff[4], w2.x, xd); ffma2(accoff[5], w2.y, xd);
                ffma2(accoff[6], w3.x, xd); ffma2(accoff[7], w3.y, xd);
                ffma2(accoff[8], w4.x, xd); ffma2(accoff[9], w4.y, xd);
            }
        }
    }

    // ---- Phase B: bilinear sampling + 16x16x9 einsum (packed over o-pairs) ----
    u64 acc[8];
    #pragma unroll
    for (int op = 0; op < 8; op++) acc[op] = 0ULL;

    #pragma unroll 1
    for (int k = 0; k < 9; k++) {
        const float2 off = unpack2(accoff[k]);
        const float py = (float)(h - 1 + k / 3) + off.x;
        const float px = (float)(w - 1 + k % 3) + off.y;
        const float y0f = floorf(py), x0f = floorf(px);
        const float ly = py - y0f, lx = px - x0f;
        const int y0 = (int)y0f, x0 = (int)x0f;

        const bool vy0 = (y0 >= 0)  && (y0 < H_);
        const bool vy1 = (y0 >= -1) && (y0 < H_ - 1);
        const bool vx0 = (x0 >= 0)  && (x0 < W_);
        const bool vx1 = (x0 >= -1) && (x0 < W_ - 1);

        const float w00 = (1.f - ly) * (1.f - lx) * ((vy0 && vx0) ? 1.f : 0.f);
        const float w01 = (1.f - ly) * lx         * ((vy0 && vx1) ? 1.f : 0.f);
        const float w10 = ly * (1.f - lx)         * ((vy1 && vx0) ? 1.f : 0.f);
        const float w11 = ly * lx                 * ((vy1 && vx1) ? 1.f : 0.f);

        const int yc0 = min(max(y0, 0), H_ - 1);
        const int yc1 = min(max(y0 + 1, 0), H_ - 1);
        const int xc0 = min(max(x0, 0), W_ - 1);
        const int xc1 = min(max(x0 + 1, 0), W_ - 1);

        const float4* q00 = reinterpret_cast<const float4*>(xtg + (yc0 * 64 + xc0) * 16);
        const float4* q01 = reinterpret_cast<const float4*>(xtg + (yc0 * 64 + xc1) * 16);
        const float4* q10 = reinterpret_cast<const float4*>(xtg + (yc1 * 64 + xc0) * 16);
        const float4* q11 = reinterpret_cast<const float4*>(xtg + (yc1 * 64 + xc1) * 16);
        const ulonglong2* wep = reinterpret_cast<const ulonglong2*>(&swe[k * 128]);

        // interleaved load->compute per channel-quad: low register pressure
        #pragma unroll
        for (int j = 0; j < 4; j++) {
            const float4 a = q00[j], b = q01[j], c4 = q10[j], d = q11[j];
            const float va[4] = {a.x, a.y, a.z, a.w};
            const float vb[4] = {b.x, b.y, b.z, b.w};
            const float vc[4] = {c4.x, c4.y, c4.z, c4.w};
            const float vd[4] = {d.x, d.y, d.z, d.w};
            #pragma unroll
            for (int q = 0; q < 4; q++) {
                const int c = 4 * j + q;
                const float v = fmaf(w11, vd[q], fmaf(w10, vc[q],
                                fmaf(w01, vb[q], w00 * va[q])));
                const u64 vdup = dup2(v);
                const ulonglong2 e0 = wep[c * 4 + 0];
                const ulonglong2 e1 = wep[c * 4 + 1];
                const ulonglong2 e2 = wep[c * 4 + 2];
                const ulonglong2 e3 = wep[c * 4 + 3];
                ffma2(acc[0], e0.x, vdup); ffma2(acc[1], e0.y, vdup);
                ffma2(acc[2], e1.x, vdup); ffma2(acc[3], e1.y, vdup);
                ffma2(acc[4], e2.x, vdup); ffma2(acc[5], e2.y, vdup);
                ffma2(acc[6], e3.x, vdup); ffma2(acc[7], e3.y, vdup);
            }
        }
    }

    // ---- write pre-norm output + stats ----
    float ov[16];
    #pragma unroll
    for (int op = 0; op < 8; op++) {
        const float2 t = unpack2(acc[op]);
        ov[2 * op] = t.x; ov[2 * op + 1] = t.y;
    }
    float* pre = g_pre + ((size_t)(n * 64 + g * 16)) * HW + p;
    #pragma unroll
    for (int o = 0; o < 16; o++) pre[(size_t)o * HW] = ov[o];

    const int lane = tid & 31;
    #pragma unroll
    for (int o = 0; o < 16; o++) {
        float s = ov[o];
        float q = ov[o] * ov[o];
        #pragma unroll
        for (int d = 16; d; d >>= 1) {
            s += __shfl_xor_sync(0xffffffffu, s, d);
            q += __shfl_xor_sync(0xffffffffu, q, d);
        }
        if (lane == 0) { atomicAdd(&s_sum[o], s); atomicAdd(&s_sq[o], q); }
    }
    __syncthreads();
    if (tid < 16) {
        atomicAdd(&g_sum[n * 64 + g * 16 + tid], s_sum[tid]);
        atomicAdd(&g_sq [n * 64 + g * 16 + tid], s_sq[tid]);
    }
}

// Normalize + exact GELU + transposed store (vectorized float4)
__global__ void norm_gelu_kernel(float* __restrict__ out) {
    const int oc = blockIdx.y;
    const int n  = blockIdx.z;
    const int p4 = blockIdx.x * blockDim.x + threadIdx.x;   // 0..1023

    const float s = g_sum[n * 64 + oc];
    const float q = g_sq [n * 64 + oc];
    const float mean = s * (1.f / HW);
    const float var  = q * (1.f / HW) - mean * mean;
    const float inv  = rsqrtf(var + 1e-5f);

    const float4 v = reinterpret_cast<const float4*>(g_pre + ((size_t)(n * 64 + oc)) * HW)[p4];
    float4 r;
    { const float a = (v.x - mean) * inv; r.x = 0.5f * a * (1.f + erff(a * 0.7071067811865475f)); }
    { const float a = (v.y - mean) * inv; r.y = 0.5f * a * (1.f + erff(a * 0.7071067811865475f)); }
    { const float a = (v.z - mean) * inv; r.z = 0.5f * a * (1.f + erff(a * 0.7071067811865475f)); }
    { const float a = (v.w - mean) * inv; r.w = 0.5f * a * (1.f + erff(a * 0.7071067811865475f)); }

    const int b = n >> 3, d = n & 7;
    reinterpret_cast<float4*>(out + ((size_t)((b * 64 + oc) * 8 + d)) * HW)[p4] = r;
}

extern "C" void kernel_launch(void* const* d_in, const int* in_sizes, int n_in,
                              void* d_out, int out_size) {
    const float* x     = (const float*)d_in[0];
    const float* w_off = (const float*)d_in[1];
    const float* b_off = (const float*)d_in[2];
    const float* w_dc  = (const float*)d_in[3];
    // d_in[4] = b_dc: per-channel constant cancels under per-channel mean
    // subtraction; variance unchanged -> unused.
    float* out = (float*)d_out;

    zero_stats_kernel<<<(N_ * COUT + 255) / 256, 256>>>();
    transpose_kernel<<<dim3(HW / 256, G_, N_), 256>>>(x);
    fused_kernel<<<dim3(HW / 128, G_, N_), 128>>>(w_off, b_off, w_dc);
    norm_gelu_kernel<<<dim3(HW / (256 * 4), COUT, N_), 256>>>(out);
}

// round 4
// speedup vs baseline: 1.1143x; 1.1143x over previous
#include <cuda_runtime.h>
#include <math.h>

#define G_   4
#define H_   64
#define W_   64
#define HW   4096
#define N_   32
#define THREADS 128
#define PPT  4      // pixels per thread
#define PIXB 512    // pixels per block

typedef unsigned long long u64;

// Scratch (static device globals; no runtime allocation)
__device__ float g_xt  [N_ * G_ * HW * 16];   // x transposed: [n][g][p][c]
__device__ float g_pre [N_ * 64 * HW];        // pre-norm conv output (b_dc cancels)
__device__ float g_part[N_ * G_ * 8 * 32];    // per-block partial sums: [n][g][bx][sum16|sq16]

// ---- packed f32x2 helpers (Blackwell) ----
__device__ __forceinline__ u64 pack2(float lo, float hi) {
    u64 r; asm("mov.b64 %0,{%1,%2};" : "=l"(r) : "f"(lo), "f"(hi)); return r;
}
__device__ __forceinline__ float2 unpack2(u64 v) {
    float2 r; asm("mov.b64 {%0,%1},%2;" : "=f"(r.x), "=f"(r.y) : "l"(v)); return r;
}
__device__ __forceinline__ void ffma2(u64 &d, u64 a, u64 b) {
    asm("fma.rn.f32x2 %0,%1,%2,%0;" : "+l"(d) : "l"(a), "l"(b));
}
__device__ __forceinline__ u64 mul2(u64 a, u64 b) {
    u64 r; asm("mul.rn.f32x2 %0,%1,%2;" : "=l"(r) : "l"(a), "l"(b)); return r;
}
__device__ __forceinline__ u64 dup2(float v) { return pack2(v, v); }

// x[n][c][p] -> x_t[n][g][p][cg]
__global__ void transpose_kernel(const float* __restrict__ x) {
    const int p = blockIdx.x * 256 + threadIdx.x;
    const int g = blockIdx.y, n = blockIdx.z;
    const float* xs = x + ((size_t)(n * 64 + g * 16)) * HW + p;
    float v[16];
    #pragma unroll
    for (int c = 0; c < 16; c++) v[c] = __ldg(xs + (size_t)c * HW);
    float4* dst = reinterpret_cast<float4*>(g_xt + (((size_t)(n * 4 + g)) * HW + p) * 16);
    dst[0] = make_float4(v[0],  v[1],  v[2],  v[3]);
    dst[1] = make_float4(v[4],  v[5],  v[6],  v[7]);
    dst[2] = make_float4(v[8],  v[9],  v[10], v[11]);
    dst[3] = make_float4(v[12], v[13], v[14], v[15]);
}

// One k-chunk: offset conv for taps [KBASE, KBASE+S) then immediate deformable
// sampling + einsum for those taps. Offsets stay in registers.
template<int KBASE, int S>
__device__ __forceinline__ void do_chunk(
    u64 acc[PPT][8], const float* __restrict__ xtg,
    const u64* __restrict__ swc, const u64* __restrict__ swe,
    const u64* __restrict__ sb, int h0, int w0)
{
    // ---- Phase A: conv accumulation for this chunk's taps ----
    u64 ao[PPT][S];
    #pragma unroll
    for (int pix = 0; pix < PPT; pix++)
        #pragma unroll
        for (int kk = 0; kk < S; kk++) ao[pix][kk] = sb[KBASE + kk];

    #pragma unroll 1
    for (int pos = 0; pos < 9; pos++) {
        const int xx = w0 + pos % 3 - 1;
        const bool vx = (unsigned)xx < 64u;
        const int yb = h0 + pos / 3 - 1;
        // per (pos,c): S u64 weights at swc[(pos*16+c)*10 + KBASE]
        const u64* wp = swc + (pos * 16) * 10 + KBASE;
        #pragma unroll
        for (int j = 0; j < 4; j++) {
            float4 X[PPT];
            #pragma unroll
            for (int pix = 0; pix < PPT; pix++) {
                const int y = yb + 2 * pix;
                X[pix] = make_float4(0.f, 0.f, 0.f, 0.f);
                if (vx && (unsigned)y < 64u)
                    X[pix] = *(reinterpret_cast<const float4*>(xtg + (y * 64 + xx) * 16) + j);
            }
            #pragma unroll
            for (int q = 0; q < 4; q++) {
                const int c = 4 * j + q;
                const ulonglong2* wv = reinterpret_cast<const ulonglong2*>(wp + c * 10);
                u64 wreg[S];
                if (S == 4) {
                    const ulonglong2 wA = wv[0], wB = wv[1];
                    wreg[0] = wA.x; wreg[1] = wA.y; wreg[2] = wB.x; wreg[3] = wB.y;
                } else { // S==2, KBASE=8 -> u64 idx 8,9 = ulonglong2 idx 4
                    const ulonglong2 wA = wv[0];
                    wreg[0] = wA.x; wreg[1] = wA.y;
                }
                #pragma unroll
                for (int pix = 0; pix < PPT; pix++) {
                    const float xv = (q == 0) ? X[pix].x : (q == 1) ? X[pix].y
                                   : (q == 2) ? X[pix].z : X[pix].w;
                    const u64 xd = dup2(xv);
                    #pragma unroll
                    for (int kk = 0; kk < S; kk++) ffma2(ao[pix][kk], wreg[kk], xd);
                }
            }
        }
    }

    // ---- Phase B: sampling + einsum for this chunk's real taps ----
    #pragma unroll
    for (int kk = 0; kk < S; kk++) {
        const int k = KBASE + kk;
        if (k >= 9) break;
        int ofs[PPT][4];
        u64 wwd[PPT][4];
        #pragma unroll
        for (int pix = 0; pix < PPT; pix++) {
            const float2 off = unpack2(ao[pix][kk]);
            const float py = (float)(h0 + 2 * pix - 1 + k / 3) + off.x;
            const float px = (float)(w0 - 1 + k % 3) + off.y;
            const float y0f = floorf(py), x0f = floorf(px);
            const float ly = py - y0f, lx = px - x0f;
            const int y0 = (int)y0f, x0 = (int)x0f;
            const bool vy0 = (y0 >= 0)  && (y0 < 64);
            const bool vy1 = (y0 >= -1) && (y0 < 63);
            const bool vx0 = (x0 >= 0)  && (x0 < 64);
            const bool vx1 = (x0 >= -1) && (x0 < 63);
            const float w00 = (1.f - ly) * (1.f - lx) * ((vy0 && vx0) ? 1.f : 0.f);
            const float w01 = (1.f - ly) * lx         * ((vy0 && vx1) ? 1.f : 0.f);
            const float w10 = ly * (1.f - lx)         * ((vy1 && vx0) ? 1.f : 0.f);
            const float w11 = ly * lx                 * ((vy1 && vx1) ? 1.f : 0.f);
            wwd[pix][0] = dup2(w00); wwd[pix][1] = dup2(w01);
            wwd[pix][2] = dup2(w10); wwd[pix][3] = dup2(w11);
            const int yc0 = min(max(y0, 0), 63), yc1 = min(max(y0 + 1, 0), 63);
            const int xc0 = min(max(x0, 0), 63), xc1 = min(max(x0 + 1, 0), 63);
            ofs[pix][0] = (yc0 * 64 + xc0) * 16; ofs[pix][1] = (yc0 * 64 + xc1) * 16;
            ofs[pix][2] = (yc1 * 64 + xc0) * 16; ofs[pix][3] = (yc1 * 64 + xc1) * 16;
        }
        const ulonglong2* wep = reinterpret_cast<const ulonglong2*>(swe + k * 128);
        #pragma unroll
        for (int j = 0; j < 4; j++) {
            u64 vd[PPT][4];
            #pragma unroll
            for (int pix = 0; pix < PPT; pix++) {
                const ulonglong2 a2 = *(reinterpret_cast<const ulonglong2*>(xtg + ofs[pix][0]) + j);
                const ulonglong2 b2 = *(reinterpret_cast<const ulonglong2*>(xtg + ofs[pix][1]) + j);
                const ulonglong2 c2 = *(reinterpret_cast<const ulonglong2*>(xtg + ofs[pix][2]) + j);
                const ulonglong2 d2 = *(reinterpret_cast<const ulonglong2*>(xtg + ofs[pix][3]) + j);
                u64 v01 = mul2(wwd[pix][0], a2.x);
                ffma2(v01, wwd[pix][1], b2.x);
                ffma2(v01, wwd[pix][2], c2.x);
                ffma2(v01, wwd[pix][3], d2.x);
                u64 v23 = mul2(wwd[pix][0], a2.y);
                ffma2(v23, wwd[pix][1], b2.y);
                ffma2(v23, wwd[pix][2], c2.y);
                ffma2(v23, wwd[pix][3], d2.y);
                const float2 t01 = unpack2(v01), t23 = unpack2(v23);
                vd[pix][0] = dup2(t01.x); vd[pix][1] = dup2(t01.y);
                vd[pix][2] = dup2(t23.x); vd[pix][3] = dup2(t23.y);
            }
            #pragma unroll
            for (int q = 0; q < 4; q++) {
                const int c = 4 * j + q;
                const ulonglong2 e0 = wep[c * 4 + 0], e1 = wep[c * 4 + 1];
                const ulonglong2 e2 = wep[c * 4 + 2], e3 = wep[c * 4 + 3];
                #pragma unroll
                for (int pix = 0; pix < PPT; pix++) {
                    const u64 v = vd[pix][q];
                    ffma2(acc[pix][0], e0.x, v); ffma2(acc[pix][1], e0.y, v);
                    ffma2(acc[pix][2], e1.x, v); ffma2(acc[pix][3], e1.y, v);
                    ffma2(acc[pix][4], e2.x, v); ffma2(acc[pix][5], e2.y, v);
                    ffma2(acc[pix][6], e3.x, v); ffma2(acc[pix][7], e3.y, v);
                }
            }
        }
    }
}

__global__ __launch_bounds__(THREADS) void fused_kernel(const float* __restrict__ w_off,
                                                        const float* __restrict__ b_off,
                                                        const float* __restrict__ w_dc) {
    __shared__ __align__(16) u64 swc[9 * 16 * 10];  // [pos][c][k10] (k 9 + 1 pad)
    __shared__ __align__(16) u64 swe[9 * 16 * 8];   // [k][c][op-pair]
    __shared__ u64 sb[10];
    __shared__ float s_red[4][32];

    const int tid = threadIdx.x;
    const int bx = blockIdx.x, g = blockIdx.y, n = blockIdx.z;

    for (int i = tid; i < 9 * 16 * 10; i += THREADS) {
        const int pos = i / 160, c = (i / 10) % 16, k = i % 10;
        u64 v = 0ULL;
        if (k < 9)
            v = pack2(w_off[((g * 18 + 2 * k)     * 16 + c) * 9 + pos],
                      w_off[((g * 18 + 2 * k + 1) * 16 + c) * 9 + pos]);
        swc[i] = v;
    }
    for (int i = tid; i < 9 * 16 * 8; i += THREADS) {
        const int k = i / 128, c = (i / 8) % 16, op = i % 8;
        swe[i] = pack2(w_dc[((g * 16 + 2 * op)     * 16 + c) * 9 + k],
                       w_dc[((g * 16 + 2 * op + 1) * 16 + c) * 9 + k]);
    }
    if (tid < 10)
        sb[tid] = (tid < 9) ? pack2(b_off[g * 18 + 2 * tid], b_off[g * 18 + 2 * tid + 1]) : 0ULL;
    __syncthreads();

    const int p0 = bx * PIXB + tid;
    const int h0 = p0 >> 6, w0 = p0 & 63;
    const float* xtg = g_xt + ((size_t)(n * 4 + g)) * HW * 16;

    u64 acc[PPT][8];
    #pragma unroll
    for (int pix = 0; pix < PPT; pix++)
        #pragma unroll
        for (int op = 0; op < 8; op++) acc[pix][op] = 0ULL;

    do_chunk<0, 4>(acc, xtg, swc, swe, sb, h0, w0);
    do_chunk<4, 4>(acc, xtg, swc, swe, sb, h0, w0);
    do_chunk<8, 2>(acc, xtg, swc, swe, sb, h0, w0);

    // ---- write pre-norm output + block-local stats ----
    float sv[16], sq[16];
    #pragma unroll
    for (int o = 0; o < 16; o++) { sv[o] = 0.f; sq[o] = 0.f; }
    #pragma unroll
    for (int pix = 0; pix < PPT; pix++) {
        float* pre = g_pre + ((size_t)(n * 64 + g * 16)) * HW + p0 + pix * THREADS;
        #pragma unroll
        for (int op = 0; op < 8; op++) {
            const float2 t = unpack2(acc[pix][op]);
            pre[(size_t)(2 * op)     * HW] = t.x;
            pre[(size_t)(2 * op + 1) * HW] = t.y;
            sv[2 * op]     += t.x; sq[2 * op]     += t.x * t.x;
            sv[2 * op + 1] += t.y; sq[2 * op + 1] += t.y * t.y;
        }
    }
    const int wi = tid >> 5, lane = tid & 31;
    #pragma unroll
    for (int o = 0; o < 16; o++) {
        #pragma unroll
        for (int d = 16; d; d >>= 1) {
            sv[o] += __shfl_xor_sync(0xffffffffu, sv[o], d);
            sq[o] += __shfl_xor_sync(0xffffffffu, sq[o], d);
        }
    }
    if (lane == 0) {
        #pragma unroll
        for (int o = 0; o < 16; o++) { s_red[wi][o] = sv[o]; s_red[wi][16 + o] = sq[o]; }
    }
    __syncthreads();
    if (tid < 32) {
        const float v = s_red[0][tid] + s_red[1][tid] + s_red[2][tid] + s_red[3][tid];
        g_part[(((n * 4 + g) * 8) + bx) * 32 + tid] = v;
    }
}

// Normalize + exact GELU + transposed store (reduces 8 block-partials)
__global__ void norm_gelu_kernel(float* __restrict__ out) {
    const int oc = blockIdx.y;
    const int n  = blockIdx.z;
    const int g = oc >> 4, o = oc & 15;

    float s = 0.f, q = 0.f;
    #pragma unroll
    for (int b = 0; b < 8; b++) {
        const float* pp = g_part + ((n * 4 + g) * 8 + b) * 32;
        s += pp[o]; q += pp[16 + o];
    }
    const float mean = s * (1.f / HW);
    const float var  = q * (1.f / HW) - mean * mean;
    const float inv  = rsqrtf(var + 1e-5f);

    const int p4 = blockIdx.x * blockDim.x + threadIdx.x;   // 0..1023
    const float4 v = reinterpret_cast<const float4*>(g_pre + ((size_t)(n * 64 + oc)) * HW)[p4];
    float4 r;
    { const float a = (v.x - mean) * inv; r.x = 0.5f * a * (1.f + erff(a * 0.7071067811865475f)); }
    { const float a = (v.y - mean) * inv; r.y = 0.5f * a * (1.f + erff(a * 0.7071067811865475f)); }
    { const float a = (v.z - mean) * inv; r.z = 0.5f * a * (1.f + erff(a * 0.7071067811865475f)); }
    { const float a = (v.w - mean) * inv; r.w = 0.5f * a * (1.f + erff(a * 0.7071067811865475f)); }

    const int b = n >> 3, d = n & 7;
    reinterpret_cast<float4*>(out + ((size_t)((b * 64 + oc) * 8 + d)) * HW)[p4] = r;
}

extern "C" void kernel_launch(void* const* d_in, const int* in_sizes, int n_in,
                              void* d_out, int out_size) {
    const float* x     = (const float*)d_in[0];
    const float* w_off = (const float*)d_in[1];
    const float* b_off = (const float*)d_in[2];
    const float* w_dc  = (const float*)d_in[3];
    // d_in[4] = b_dc: per-channel constant cancels under per-channel mean
    // subtraction; variance unchanged -> unused.
    float* out = (float*)d_out;

    transpose_kernel<<<dim3(HW / 256, G_, N_), 256>>>(x);
    fused_kernel<<<dim3(HW / PIXB, G_, N_), THREADS>>>(w_off, b_off, w_dc);
    norm_gelu_kernel<<<dim3(HW / 1024, 64, N_), 256>>>(out);
}

// round 5
// speedup vs baseline: 1.3921x; 1.2493x over previous
#include <cuda_runtime.h>
#include <math.h>

#define G_   4
#define HW   4096
#define N_   32
#define TH   32          // tile height
#define TW   16          // tile width
#define HALO 3
#define SH   (TH + 2*HALO)   // 38
#define SW   (TW + 2*HALO)   // 22
#define PSTR 20              // floats per pixel in smem (pad 16->20: conflict-free)
#define THREADS 128
#define PPT  4
#define SMEM_BYTES (SH*SW*PSTR*4)   // 66880

typedef unsigned long long u64;

// Pre-packed weights (paired for f32x2) + scratch
__device__ u64   g_swc[4*9*16*12];   // [g][pos][c][slot12]: k0-4 @0-4, k5-8 @6-9
__device__ u64   g_swe[4*9*16*8];    // [g][k][c][op-pair]
__device__ u64   g_sb [4*9];
__device__ float g_pre [N_*64*HW];
__device__ float g_part[N_*4*8*32];

// ---- packed f32x2 helpers ----
__device__ __forceinline__ u64 pack2(float lo, float hi) {
    u64 r; asm("mov.b64 %0,{%1,%2};" : "=l"(r) : "f"(lo), "f"(hi)); return r;
}
__device__ __forceinline__ float2 unpack2(u64 v) {
    float2 r; asm("mov.b64 {%0,%1},%2;" : "=f"(r.x), "=f"(r.y) : "l"(v)); return r;
}
__device__ __forceinline__ void ffma2(u64 &d, u64 a, u64 b) {
    asm("fma.rn.f32x2 %0,%1,%2,%0;" : "+l"(d) : "l"(a), "l"(b));
}
__device__ __forceinline__ u64 mul2(u64 a, u64 b) {
    u64 r; asm("mul.rn.f32x2 %0,%1,%2;" : "=l"(r) : "l"(a), "l"(b)); return r;
}
__device__ __forceinline__ u64 dup2(float v) { return pack2(v, v); }

// Pack weights into paired layouts
__global__ void prep_kernel(const float* __restrict__ w_off,
                            const float* __restrict__ b_off,
                            const float* __restrict__ w_dc) {
    const int i = blockIdx.x * 256 + threadIdx.x;
    if (i < 6912) {                       // swc: 4*9*16*12
        const int slot = i % 12, c = (i / 12) % 16, pos = (i / 192) % 9, g = i / 1728;
        int k = -1;
        if (slot < 5) k = slot;
        else if (slot >= 6 && slot <= 9) k = slot - 1;
        u64 v = 0ULL;
        if (k >= 0)
            v = pack2(w_off[((g*18 + 2*k)   * 16 + c) * 9 + pos],
                      w_off[((g*18 + 2*k+1) * 16 + c) * 9 + pos]);
        g_swc[i] = v;
    } else if (i < 6912 + 4608) {         // swe: 4*9*16*8
        const int j = i - 6912;
        const int op = j % 8, c = (j / 8) % 16, k = (j / 128) % 9, g = j / 1152;
        g_swe[j] = pack2(w_dc[((g*16 + 2*op)   * 16 + c) * 9 + k],
                         w_dc[((g*16 + 2*op+1) * 16 + c) * 9 + k]);
    } else if (i < 6912 + 4608 + 36) {    // sb
        const int j = i - 11520;
        const int k = j % 9, g = j / 9;
        g_sb[j] = pack2(b_off[g*18 + 2*k], b_off[g*18 + 2*k + 1]);
    }
}

// One k-chunk: offset conv for taps [KLO,KLO+S) reading smem tile, then
// immediate deformable sampling + einsum for those taps.
template<int KLO, int S>
__device__ __forceinline__ void chunk(
    u64 acc[PPT][8], const float* __restrict__ tile, const float* __restrict__ xg,
    const u64* __restrict__ swc_g, const u64* __restrict__ swe_g,
    const u64* __restrict__ sb_g,
    const int pixbase[PPT], int ty0, int tx0, int tid)
{
    const int lanex = tid & 15;

    // ---- Phase A: conv accumulation for this chunk's taps (smem reads) ----
    u64 ao[PPT][S];
    #pragma unroll
    for (int pix = 0; pix < PPT; pix++)
        #pragma unroll
        for (int kk = 0; kk < S; kk++) ao[pix][kk] = sb_g[KLO + kk];

    #pragma unroll 1
    for (int pos = 0; pos < 9; pos++) {
        const int dyp = pos / 3, dxp = pos % 3;
        const int pofs = (dyp * SW + dxp) * PSTR;
        const u64* wb0 = swc_g + (pos * 16) * 12;
        #pragma unroll
        for (int j = 0; j < 4; j++) {
            float4 X[PPT];
            #pragma unroll
            for (int pix = 0; pix < PPT; pix++)
                X[pix] = *reinterpret_cast<const float4*>(tile + pixbase[pix] + pofs + 4*j);
            #pragma unroll
            for (int q = 0; q < 4; q++) {
                const u64* wb = wb0 + (4*j + q) * 12;
                u64 wr[S];
                if (S == 5) {
                    const ulonglong2 a = *reinterpret_cast<const ulonglong2*>(wb);
                    const ulonglong2 b = *reinterpret_cast<const ulonglong2*>(wb + 2);
                    wr[0] = a.x; wr[1] = a.y; wr[2] = b.x; wr[3] = b.y; wr[4] = wb[4];
                } else {
                    const ulonglong2 a = *reinterpret_cast<const ulonglong2*>(wb + 6);
                    const ulonglong2 b = *reinterpret_cast<const ulonglong2*>(wb + 8);
                    wr[0] = a.x; wr[1] = a.y; wr[2] = b.x; wr[3] = b.y;
                }
                #pragma unroll
                for (int pix = 0; pix < PPT; pix++) {
                    const float xv = (q == 0) ? X[pix].x : (q == 1) ? X[pix].y
                                   : (q == 2) ? X[pix].z : X[pix].w;
                    const u64 xd = dup2(xv);
                    #pragma unroll
                    for (int kk = 0; kk < S; kk++) ffma2(ao[pix][kk], wr[kk], xd);
                }
            }
        }
    }

    // ---- Phase B: sampling (smem, with rare global fallback) + einsum ----
    const int oy = ty0 - HALO, ox = tx0 - HALO;
    #pragma unroll 1
    for (int kk = 0; kk < S; kk++) {
        const int k = KLO + kk;
        const int kdy = k / 3 - 1, kdx = k % 3 - 1;
        u64 wwd[PPT][4];
        int cw[PPT][4];
        bool inw[PPT];
        #pragma unroll
        for (int pix = 0; pix < PPT; pix++) {
            const float2 off = unpack2(ao[pix][kk]);
            const int hg = ty0 + (tid >> 4) + 8 * pix;
            const int wg = tx0 + lanex;
            const float py = (float)(hg + kdy) + off.x;
            const float px = (float)(wg + kdx) + off.y;
            const float y0f = floorf(py), x0f = floorf(px);
            const float fy = py - y0f, fx = px - x0f;
            const int y0 = (int)y0f, x0 = (int)x0f;
            const bool vy0 = (y0 >= 0)  && (y0 < 64);
            const bool vy1 = (y0 >= -1) && (y0 < 63);
            const bool vx0 = (x0 >= 0)  && (x0 < 64);
            const bool vx1 = (x0 >= -1) && (x0 < 63);
            wwd[pix][0] = dup2((1.f - fy) * (1.f - fx) * ((vy0 && vx0) ? 1.f : 0.f));
            wwd[pix][1] = dup2((1.f - fy) * fx         * ((vy0 && vx1) ? 1.f : 0.f));
            wwd[pix][2] = dup2(fy * (1.f - fx)         * ((vy1 && vx0) ? 1.f : 0.f));
            wwd[pix][3] = dup2(fy * fx                 * ((vy1 && vx1) ? 1.f : 0.f));
            const int yc0 = min(max(y0, 0), 63), yc1 = min(max(y0 + 1, 0), 63);
            const int xc0 = min(max(x0, 0), 63), xc1 = min(max(x0 + 1, 0), 63);
            const int t0y = yc0 - oy, t1y = yc1 - oy;
            const int t0x = xc0 - ox, t1x = xc1 - ox;
            const bool win = (t0y >= 0) && (t1y < SH) && (t0x >= 0) && (t1x < SW);
            inw[pix] = win;
            if (win) {
                cw[pix][0] = (t0y * SW + t0x) * PSTR; cw[pix][1] = (t0y * SW + t1x) * PSTR;
                cw[pix][2] = (t1y * SW + t0x) * PSTR; cw[pix][3] = (t1y * SW + t1x) * PSTR;
            } else {   // global pixel indices (rare path)
                cw[pix][0] = yc0 * 64 + xc0; cw[pix][1] = yc0 * 64 + xc1;
                cw[pix][2] = yc1 * 64 + xc0; cw[pix][3] = yc1 * 64 + xc1;
            }
        }
        const u64* web = swe_g + (k * 16) * 8;
        #pragma unroll
        for (int j = 0; j < 4; j++) {
            u64 vd[PPT][4];
            #pragma unroll
            for (int pix = 0; pix < PPT; pix++) {
                ulonglong2 A2, B2, C2, D2;
                if (inw[pix]) {
                    A2 = *reinterpret_cast<const ulonglong2*>(tile + cw[pix][0] + 4*j);
                    B2 = *reinterpret_cast<const ulonglong2*>(tile + cw[pix][1] + 4*j);
                    C2 = *reinterpret_cast<const ulonglong2*>(tile + cw[pix][2] + 4*j);
                    D2 = *reinterpret_cast<const ulonglong2*>(tile + cw[pix][3] + 4*j);
                } else {
                    const float* xq = xg + (size_t)(4*j) * HW;
                    const int i0 = cw[pix][0], i1 = cw[pix][1], i2 = cw[pix][2], i3 = cw[pix][3];
                    A2.x = pack2(xq[i0], xq[HW + i0]); A2.y = pack2(xq[2*HW + i0], xq[3*HW + i0]);
                    B2.x = pack2(xq[i1], xq[HW + i1]); B2.y = pack2(xq[2*HW + i1], xq[3*HW + i1]);
                    C2.x = pack2(xq[i2], xq[HW + i2]); C2.y = pack2(xq[2*HW + i2], xq[3*HW + i2]);
                    D2.x = pack2(xq[i3], xq[HW + i3]); D2.y = pack2(xq[2*HW + i3], xq[3*HW + i3]);
                }
                u64 v01 = mul2(wwd[pix][0], A2.x);
                ffma2(v01, wwd[pix][1], B2.x);
                ffma2(v01, wwd[pix][2], C2.x);
                ffma2(v01, wwd[pix][3], D2.x);
                u64 v23 = mul2(wwd[pix][0], A2.y);
                ffma2(v23, wwd[pix][1], B2.y);
                ffma2(v23, wwd[pix][2], C2.y);
                ffma2(v23, wwd[pix][3], D2.y);
                const float2 t01 = unpack2(v01), t23 = unpack2(v23);
                vd[pix][0] = dup2(t01.x); vd[pix][1] = dup2(t01.y);
                vd[pix][2] = dup2(t23.x); vd[pix][3] = dup2(t23.y);
            }
            #pragma unroll
            for (int q = 0; q < 4; q++) {
                const ulonglong2* we2 =
                    reinterpret_cast<const ulonglong2*>(web + (4*j + q) * 8);
                const ulonglong2 e0 = we2[0], e1 = we2[1], e2 = we2[2], e3 = we2[3];
                #pragma unroll
                for (int pix = 0; pix < PPT; pix++) {
                    const u64 v = vd[pix][q];
                    ffma2(acc[pix][0], e0.x, v); ffma2(acc[pix][1], e0.y, v);
                    ffma2(acc[pix][2], e1.x, v); ffma2(acc[pix][3], e1.y, v);
                    ffma2(acc[pix][4], e2.x, v); ffma2(acc[pix][5], e2.y, v);
                    ffma2(acc[pix][6], e3.x, v); ffma2(acc[pix][7], e3.y, v);
                }
            }
        }
    }
}

__global__ __launch_bounds__(THREADS) void fused_kernel(const float* __restrict__ x) {
    extern __shared__ float tile[];
    __shared__ float s_red[4][32];

    const int tid = threadIdx.x;
    const int bx = blockIdx.x, g = blockIdx.y, n = blockIdx.z;
    const int ty0 = (bx >> 2) * TH, tx0 = (bx & 3) * TW;
    const float* xg = x + ((size_t)(n * 64 + g * 16)) * HW;

    // Fill tile (zero halo outside image = conv boundary skip)
    for (int sp = tid; sp < SH * SW; sp += THREADS) {
        const int gy = ty0 - HALO + sp / SW;
        const int gx = tx0 - HALO + sp % SW;
        const bool in = ((unsigned)gy < 64u) && ((unsigned)gx < 64u);
        const int gp = gy * 64 + gx;
        #pragma unroll
        for (int c = 0; c < 16; c++)
            tile[sp * PSTR + c] = in ? xg[(size_t)c * HW + gp] : 0.f;
    }
    __syncthreads();

    const u64* swc_g = g_swc + g * (9*16*12);
    const u64* swe_g = g_swe + g * (9*16*8);
    const u64* sb_g  = g_sb  + g * 9;

    int pixbase[PPT];
    #pragma unroll
    for (int pix = 0; pix < PPT; pix++)
        pixbase[pix] = (((tid >> 4) + 8*pix + HALO - 1) * SW + (tid & 15) + HALO - 1) * PSTR;

    u64 acc[PPT][8];
    #pragma unroll
    for (int pix = 0; pix < PPT; pix++)
        #pragma unroll
        for (int op = 0; op < 8; op++) acc[pix][op] = 0ULL;

    chunk<0, 5>(acc, tile, xg, swc_g, swe_g, sb_g, pixbase, ty0, tx0, tid);
    chunk<5, 4>(acc, tile, xg, swc_g, swe_g, sb_g, pixbase, ty0, tx0, tid);

    // ---- write pre-norm output + block-local stats ----
    const int p0 = (ty0 + (tid >> 4)) * 64 + tx0 + (tid & 15);
    float sv[16], sq[16];
    #pragma unroll
    for (int o = 0; o < 16; o++) { sv[o] = 0.f; sq[o] = 0.f; }
    #pragma unroll
    for (int pix = 0; pix < PPT; pix++) {
        float* pre = g_pre + ((size_t)(n * 64 + g * 16)) * HW + p0 + pix * 8 * 64;
        #pragma unroll
        for (int op = 0; op < 8; op++) {
            const float2 t = unpack2(acc[pix][op]);
            pre[(size_t)(2*op)     * HW] = t.x;
            pre[(size_t)(2*op + 1) * HW] = t.y;
            sv[2*op]     += t.x; sq[2*op]     += t.x * t.x;
            sv[2*op + 1] += t.y; sq[2*op + 1] += t.y * t.y;
        }
    }
    const int wi = tid >> 5, lane = tid & 31;
    #pragma unroll
    for (int o = 0; o < 16; o++) {
        #pragma unroll
        for (int d = 16; d; d >>= 1) {
            sv[o] += __shfl_xor_sync(0xffffffffu, sv[o], d);
            sq[o] += __shfl_xor_sync(0xffffffffu, sq[o], d);
        }
    }
    if (lane == 0) {
        #pragma unroll
        for (int o = 0; o < 16; o++) { s_red[wi][o] = sv[o]; s_red[wi][16 + o] = sq[o]; }
    }
    __syncthreads();
    if (tid < 32) {
        const float v = s_red[0][tid] + s_red[1][tid] + s_red[2][tid] + s_red[3][tid];
        g_part[(((n * 4 + g) * 8) + bx) * 32 + tid] = v;
    }
}

// Normalize + exact GELU + transposed store
__global__ void norm_gelu_kernel(float* __restrict__ out) {
    const int oc = blockIdx.y;
    const int n  = blockIdx.z;
    const int g = oc >> 4, o = oc & 15;

    float s = 0.f, q = 0.f;
    #pragma unroll
    for (int b = 0; b < 8; b++) {
        const float* pp = g_part + ((n * 4 + g) * 8 + b) * 32;
        s += pp[o]; q += pp[16 + o];
    }
    const float mean = s * (1.f / HW);
    const float var  = q * (1.f / HW) - mean * mean;
    const float inv  = rsqrtf(var + 1e-5f);

    const int p4 = blockIdx.x * blockDim.x + threadIdx.x;
    const float4 v = reinterpret_cast<const float4*>(g_pre + ((size_t)(n * 64 + oc)) * HW)[p4];
    float4 r;
    { const float a = (v.x - mean) * inv; r.x = 0.5f * a * (1.f + erff(a * 0.7071067811865475f)); }
    { const float a = (v.y - mean) * inv; r.y = 0.5f * a * (1.f + erff(a * 0.7071067811865475f)); }
    { const float a = (v.z - mean) * inv; r.z = 0.5f * a * (1.f + erff(a * 0.7071067811865475f)); }
    { const float a = (v.w - mean) * inv; r.w = 0.5f * a * (1.f + erff(a * 0.7071067811865475f)); }

    const int b = n >> 3, d = n & 7;
    reinterpret_cast<float4*>(out + ((size_t)((b * 64 + oc) * 8 + d)) * HW)[p4] = r;
}

extern "C" void kernel_launch(void* const* d_in, const int* in_sizes, int n_in,
                              void* d_out, int out_size) {
    const float* x     = (const float*)d_in[0];
    const float* w_off = (const float*)d_in[1];
    const float* b_off = (const float*)d_in[2];
    const float* w_dc  = (const float*)d_in[3];
    // d_in[4] = b_dc: cancels exactly under per-channel mean subtraction.
    float* out = (float*)d_out;

    cudaFuncSetAttribute(fused_kernel,
                         cudaFuncAttributeMaxDynamicSharedMemorySize, SMEM_BYTES);

    prep_kernel<<<46, 256>>>(w_off, b_off, w_dc);
    fused_kernel<<<dim3(8, G_, N_), THREADS, SMEM_BYTES>>>(x);
    norm_gelu_kernel<<<dim3(HW / 1024, 64, N_), 256>>>(out);
}

// round 6
// speedup vs baseline: 1.9225x; 1.3809x over previous
#include <cuda_runtime.h>
#include <math.h>

#define G_   4
#define HW   4096
#define N_   32
#define TH   32          // tile height
#define TW   16          // tile width
#define HALO 3
#define SH   (TH + 2*HALO)   // 38
#define SW   (TW + 2*HALO)   // 22
#define PSTR 20              // floats per pixel in smem (pad 16->20: conflict-free)
#define THREADS 128
#define PPT  4

// dynamic smem carve (bytes)
#define SWC_U64   (9*16*12)          // [pos][c][slot12]: k0-4 @0-4, k5-8 @6-9
#define SWE_U64   (9*16*8)           // [k][c][op-pair]
#define SB_U64    10
#define TILE_OFF  ((SWC_U64 + SWE_U64 + SB_U64) * 8)        // 23120 B
#define SMEM_BYTES (TILE_OFF + SH*SW*PSTR*4)                // +66880 = 90000 B

typedef unsigned long long u64;

__device__ float g_pre [N_*64*HW];
__device__ float g_part[N_*4*8*32];

// ---- packed f32x2 helpers ----
__device__ __forceinline__ u64 pack2(float lo, float hi) {
    u64 r; asm("mov.b64 %0,{%1,%2};" : "=l"(r) : "f"(lo), "f"(hi)); return r;
}
__device__ __forceinline__ float2 unpack2(u64 v) {
    float2 r; asm("mov.b64 {%0,%1},%2;" : "=f"(r.x), "=f"(r.y) : "l"(v)); return r;
}
__device__ __forceinline__ void ffma2(u64 &d, u64 a, u64 b) {
    asm("fma.rn.f32x2 %0,%1,%2,%0;" : "+l"(d) : "l"(a), "l"(b));
}
__device__ __forceinline__ u64 mul2(u64 a, u64 b) {
    u64 r; asm("mul.rn.f32x2 %0,%1,%2;" : "=l"(r) : "l"(a), "l"(b)); return r;
}
__device__ __forceinline__ u64 dup2(float v) { return pack2(v, v); }

// One k-chunk: offset conv for taps [KLO,KLO+S) reading smem tile, then
// immediate deformable sampling + einsum for those taps.
template<int KLO, int S>
__device__ __forceinline__ void chunk(
    u64 acc[PPT][8], const float* __restrict__ tile, const float* __restrict__ xg,
    const u64* __restrict__ swc, const u64* __restrict__ swe,
    const u64* __restrict__ sb,
    const int pixbase[PPT], int ty0, int tx0, int tid)
{
    const int lanex = tid & 15;

    // ---- Phase A: conv accumulation for this chunk's taps (smem reads) ----
    u64 ao[PPT][S];
    #pragma unroll
    for (int pix = 0; pix < PPT; pix++)
        #pragma unroll
        for (int kk = 0; kk < S; kk++) ao[pix][kk] = sb[KLO + kk];

    #pragma unroll 1
    for (int pos = 0; pos < 9; pos++) {
        const int dyp = pos / 3, dxp = pos % 3;
        const int pofs = (dyp * SW + dxp) * PSTR;
        const u64* wb0 = swc + (pos * 16) * 12;
        #pragma unroll
        for (int j = 0; j < 4; j++) {
            float4 X[PPT];
            #pragma unroll
            for (int pix = 0; pix < PPT; pix++)
                X[pix] = *reinterpret_cast<const float4*>(tile + pixbase[pix] + pofs + 4*j);
            #pragma unroll
            for (int q = 0; q < 4; q++) {
                const u64* wb = wb0 + (4*j + q) * 12;
                u64 wr[S];
                if (S == 5) {
                    const ulonglong2 a = *reinterpret_cast<const ulonglong2*>(wb);
                    const ulonglong2 b = *reinterpret_cast<const ulonglong2*>(wb + 2);
                    wr[0] = a.x; wr[1] = a.y; wr[2] = b.x; wr[3] = b.y; wr[4] = wb[4];
                } else {
                    const ulonglong2 a = *reinterpret_cast<const ulonglong2*>(wb + 6);
                    const ulonglong2 b = *reinterpret_cast<const ulonglong2*>(wb + 8);
                    wr[0] = a.x; wr[1] = a.y; wr[2] = b.x; wr[3] = b.y;
                }
                #pragma unroll
                for (int pix = 0; pix < PPT; pix++) {
                    const float xv = (q == 0) ? X[pix].x : (q == 1) ? X[pix].y
                                   : (q == 2) ? X[pix].z : X[pix].w;
                    const u64 xd = dup2(xv);
                    #pragma unroll
                    for (int kk = 0; kk < S; kk++) ffma2(ao[pix][kk], wr[kk], xd);
                }
            }
        }
    }

    // ---- Phase B: sampling (smem, with rare global fallback) + einsum ----
    const int oy = ty0 - HALO, ox = tx0 - HALO;
    #pragma unroll 1
    for (int kk = 0; kk < S; kk++) {
        const int k = KLO + kk;
        const int kdy = k / 3 - 1, kdx = k % 3 - 1;
        u64 wwd[PPT][4];
        int cw[PPT][4];
        bool inw[PPT];
        #pragma unroll
        for (int pix = 0; pix < PPT; pix++) {
            const float2 off = unpack2(ao[pix][kk]);
            const int hg = ty0 + (tid >> 4) + 8 * pix;
            const int wg = tx0 + lanex;
            const float py = (float)(hg + kdy) + off.x;
            const float px = (float)(wg + kdx) + off.y;
            const float y0f = floorf(py), x0f = floorf(px);
            const float fy = py - y0f, fx = px - x0f;
            const int y0 = (int)y0f, x0 = (int)x0f;
            const bool vy0 = (y0 >= 0)  && (y0 < 64);
            const bool vy1 = (y0 >= -1) && (y0 < 63);
            const bool vx0 = (x0 >= 0)  && (x0 < 64);
            const bool vx1 = (x0 >= -1) && (x0 < 63);
            wwd[pix][0] = dup2((1.f - fy) * (1.f - fx) * ((vy0 && vx0) ? 1.f : 0.f));
            wwd[pix][1] = dup2((1.f - fy) * fx         * ((vy0 && vx1) ? 1.f : 0.f));
            wwd[pix][2] = dup2(fy * (1.f - fx)         * ((vy1 && vx0) ? 1.f : 0.f));
            wwd[pix][3] = dup2(fy * fx                 * ((vy1 && vx1) ? 1.f : 0.f));
            const int yc0 = min(max(y0, 0), 63), yc1 = min(max(y0 + 1, 0), 63);
            const int xc0 = min(max(x0, 0), 63), xc1 = min(max(x0 + 1, 0), 63);
            const int t0y = yc0 - oy, t1y = yc1 - oy;
            const int t0x = xc0 - ox, t1x = xc1 - ox;
            const bool win = (t0y >= 0) && (t1y < SH) && (t0x >= 0) && (t1x < SW);
            inw[pix] = win;
            if (win) {
                cw[pix][0] = (t0y * SW + t0x) * PSTR; cw[pix][1] = (t0y * SW + t1x) * PSTR;
                cw[pix][2] = (t1y * SW + t0x) * PSTR; cw[pix][3] = (t1y * SW + t1x) * PSTR;
            } else {   // global pixel indices (rare path)
                cw[pix][0] = yc0 * 64 + xc0; cw[pix][1] = yc0 * 64 + xc1;
                cw[pix][2] = yc1 * 64 + xc0; cw[pix][3] = yc1 * 64 + xc1;
            }
        }
        const u64* web = swe + (k * 16) * 8;
        #pragma unroll
        for (int j = 0; j < 4; j++) {
            u64 vd[PPT][4];
            #pragma unroll
            for (int pix = 0; pix < PPT; pix++) {
                ulonglong2 A2, B2, C2, D2;
                if (inw[pix]) {
                    A2 = *reinterpret_cast<const ulonglong2*>(tile + cw[pix][0] + 4*j);
                    B2 = *reinterpret_cast<const ulonglong2*>(tile + cw[pix][1] + 4*j);
                    C2 = *reinterpret_cast<const ulonglong2*>(tile + cw[pix][2] + 4*j);
                    D2 = *reinterpret_cast<const ulonglong2*>(tile + cw[pix][3] + 4*j);
                } else {
                    const float* xq = xg + (size_t)(4*j) * HW;
                    const int i0 = cw[pix][0], i1 = cw[pix][1], i2 = cw[pix][2], i3 = cw[pix][3];
                    A2.x = pack2(xq[i0], xq[HW + i0]); A2.y = pack2(xq[2*HW + i0], xq[3*HW + i0]);
                    B2.x = pack2(xq[i1], xq[HW + i1]); B2.y = pack2(xq[2*HW + i1], xq[3*HW + i1]);
                    C2.x = pack2(xq[i2], xq[HW + i2]); C2.y = pack2(xq[2*HW + i2], xq[3*HW + i2]);
                    D2.x = pack2(xq[i3], xq[HW + i3]); D2.y = pack2(xq[2*HW + i3], xq[3*HW + i3]);
                }
                u64 v01 = mul2(wwd[pix][0], A2.x);
                ffma2(v01, wwd[pix][1], B2.x);
                ffma2(v01, wwd[pix][2], C2.x);
                ffma2(v01, wwd[pix][3], D2.x);
                u64 v23 = mul2(wwd[pix][0], A2.y);
                ffma2(v23, wwd[pix][1], B2.y);
                ffma2(v23, wwd[pix][2], C2.y);
                ffma2(v23, wwd[pix][3], D2.y);
                const float2 t01 = unpack2(v01), t23 = unpack2(v23);
                vd[pix][0] = dup2(t01.x); vd[pix][1] = dup2(t01.y);
                vd[pix][2] = dup2(t23.x); vd[pix][3] = dup2(t23.y);
            }
            #pragma unroll
            for (int q = 0; q < 4; q++) {
                const ulonglong2* we2 =
                    reinterpret_cast<const ulonglong2*>(web + (4*j + q) * 8);
                const ulonglong2 e0 = we2[0], e1 = we2[1], e2 = we2[2], e3 = we2[3];
                #pragma unroll
                for (int pix = 0; pix < PPT; pix++) {
                    const u64 v = vd[pix][q];
                    ffma2(acc[pix][0], e0.x, v); ffma2(acc[pix][1], e0.y, v);
                    ffma2(acc[pix][2], e1.x, v); ffma2(acc[pix][3], e1.y, v);
                    ffma2(acc[pix][4], e2.x, v); ffma2(acc[pix][5], e2.y, v);
                    ffma2(acc[pix][6], e3.x, v); ffma2(acc[pix][7], e3.y, v);
                }
            }
        }
    }
}

__global__ __launch_bounds__(THREADS) void fused_kernel(const float* __restrict__ x,
                                                        const float* __restrict__ w_off,
                                                        const float* __restrict__ b_off,
                                                        const float* __restrict__ w_dc) {
    extern __shared__ __align__(16) char smem_raw[];
    u64*   swc  = reinterpret_cast<u64*>(smem_raw);
    u64*   swe  = swc + SWC_U64;
    u64*   sb   = swe + SWE_U64;
    float* tile = reinterpret_cast<float*>(smem_raw + TILE_OFF);
    __shared__ float s_red[4][32];

    const int tid = threadIdx.x;
    const int bx = blockIdx.x, g = blockIdx.y, n = blockIdx.z;
    const int ty0 = (bx >> 2) * TH, tx0 = (bx & 3) * TW;
    const float* xg = x + ((size_t)(n * 64 + g * 16)) * HW;

    // Pack weights into smem (paired for f32x2)
    for (int i = tid; i < SWC_U64; i += THREADS) {
        const int slot = i % 12, c = (i / 12) % 16, pos = i / 192;
        int k = -1;
        if (slot < 5) k = slot;
        else if (slot >= 6 && slot <= 9) k = slot - 1;
        u64 v = 0ULL;
        if (k >= 0)
            v = pack2(w_off[((g*18 + 2*k)   * 16 + c) * 9 + pos],
                      w_off[((g*18 + 2*k+1) * 16 + c) * 9 + pos]);
        swc[i] = v;
    }
    for (int i = tid; i < SWE_U64; i += THREADS) {
        const int op = i % 8, c = (i / 8) % 16, k = i / 128;
        swe[i] = pack2(w_dc[((g*16 + 2*op)   * 16 + c) * 9 + k],
                       w_dc[((g*16 + 2*op+1) * 16 + c) * 9 + k]);
    }
    if (tid < SB_U64)
        sb[tid] = (tid < 9) ? pack2(b_off[g*18 + 2*tid], b_off[g*18 + 2*tid + 1]) : 0ULL;

    // Fill tile (zero halo outside image = conv boundary skip)
    for (int sp = tid; sp < SH * SW; sp += THREADS) {
        const int gy = ty0 - HALO + sp / SW;
        const int gx = tx0 - HALO + sp % SW;
        const bool in = ((unsigned)gy < 64u) && ((unsigned)gx < 64u);
        const int gp = gy * 64 + gx;
        #pragma unroll
        for (int c = 0; c < 16; c++)
            tile[sp * PSTR + c] = in ? xg[(size_t)c * HW + gp] : 0.f;
    }
    __syncthreads();

    int pixbase[PPT];
    #pragma unroll
    for (int pix = 0; pix < PPT; pix++)
        pixbase[pix] = (((tid >> 4) + 8*pix + HALO - 1) * SW + (tid & 15) + HALO - 1) * PSTR;

    u64 acc[PPT][8];
    #pragma unroll
    for (int pix = 0; pix < PPT; pix++)
        #pragma unroll
        for (int op = 0; op < 8; op++) acc[pix][op] = 0ULL;

    chunk<0, 5>(acc, tile, xg, swc, swe, sb, pixbase, ty0, tx0, tid);
    chunk<5, 4>(acc, tile, xg, swc, swe, sb, pixbase, ty0, tx0, tid);

    // ---- write pre-norm output + block-local stats ----
    const int p0 = (ty0 + (tid >> 4)) * 64 + tx0 + (tid & 15);
    float sv[16], sq[16];
    #pragma unroll
    for (int o = 0; o < 16; o++) { sv[o] = 0.f; sq[o] = 0.f; }
    #pragma unroll
    for (int pix = 0; pix < PPT; pix++) {
        float* pre = g_pre + ((size_t)(n * 64 + g * 16)) * HW + p0 + pix * 8 * 64;
        #pragma unroll
        for (int op = 0; op < 8; op++) {
            const float2 t = unpack2(acc[pix][op]);
            pre[(size_t)(2*op)     * HW] = t.x;
            pre[(size_t)(2*op + 1) * HW] = t.y;
            sv[2*op]     += t.x; sq[2*op]     += t.x * t.x;
            sv[2*op + 1] += t.y; sq[2*op + 1] += t.y * t.y;
        }
    }
    const int wi = tid >> 5, lane = tid & 31;
    #pragma unroll
    for (int o = 0; o < 16; o++) {
        #pragma unroll
        for (int d = 16; d; d >>= 1) {
            sv[o] += __shfl_xor_sync(0xffffffffu, sv[o], d);
            sq[o] += __shfl_xor_sync(0xffffffffu, sq[o], d);
        }
    }
    if (lane == 0) {
        #pragma unroll
        for (int o = 0; o < 16; o++) { s_red[wi][o] = sv[o]; s_red[wi][16 + o] = sq[o]; }
    }
    __syncthreads();
    if (tid < 32) {
        const float v = s_red[0][tid] + s_red[1][tid] + s_red[2][tid] + s_red[3][tid];
        g_part[(((n * 4 + g) * 8) + bx) * 32 + tid] = v;
    }
}

// Normalize + exact GELU + transposed store
__global__ void norm_gelu_kernel(float* __restrict__ out) {
    const int oc = blockIdx.y;
    const int n  = blockIdx.z;
    const int g = oc >> 4, o = oc & 15;

    float s = 0.f, q = 0.f;
    #pragma unroll
    for (int b = 0; b < 8; b++) {
        const float* pp = g_part + ((n * 4 + g) * 8 + b) * 32;
        s += pp[o]; q += pp[16 + o];
    }
    const float mean = s * (1.f / HW);
    const float var  = q * (1.f / HW) - mean * mean;
    const float inv  = rsqrtf(var + 1e-5f);

    const int p4 = blockIdx.x * blockDim.x + threadIdx.x;
    const float4 v = reinterpret_cast<const float4*>(g_pre + ((size_t)(n * 64 + oc)) * HW)[p4];
    float4 r;
    { const float a = (v.x - mean) * inv; r.x = 0.5f * a * (1.f + erff(a * 0.7071067811865475f)); }
    { const float a = (v.y - mean) * inv; r.y = 0.5f * a * (1.f + erff(a * 0.7071067811865475f)); }
    { const float a = (v.z - mean) * inv; r.z = 0.5f * a * (1.f + erff(a * 0.7071067811865475f)); }
    { const float a = (v.w - mean) * inv; r.w = 0.5f * a * (1.f + erff(a * 0.7071067811865475f)); }

    const int b = n >> 3, d = n & 7;
    reinterpret_cast<float4*>(out + ((size_t)((b * 64 + oc) * 8 + d)) * HW)[p4] = r;
}

extern "C" void kernel_launch(void* const* d_in, const int* in_sizes, int n_in,
                              void* d_out, int out_size) {
    const float* x     = (const float*)d_in[0];
    const float* w_off = (const float*)d_in[1];
    const float* b_off = (const float*)d_in[2];
    const float* w_dc  = (const float*)d_in[3];
    // d_in[4] = b_dc: cancels exactly under per-channel mean subtraction.
    float* out = (float*)d_out;

    cudaFuncSetAttribute(fused_kernel,
                         cudaFuncAttributeMaxDynamicSharedMemorySize, SMEM_BYTES);

    fused_kernel<<<dim3(8, G_, N_), THREADS, SMEM_BYTES>>>(x, w_off, b_off, w_dc);
    norm_gelu_kernel<<<dim3(HW / 1024, 64, N_), 256>>>(out);
}

// round 7
// speedup vs baseline: 2.0358x; 1.0590x over previous
#include <cuda_runtime.h>
#include <math.h>

#define G_   4
#define HW   4096
#define N_   32
#define TH   32          // tile height
#define TW   16          // tile width
#define HALO 3
#define SH   (TH + 2*HALO)   // 38
#define SW   (TW + 2*HALO)   // 22
#define PSTR 20              // floats per pixel in smem (pad 16->20: conflict-free)
#define THREADS 128
#define PPT  4

// dynamic smem carve (bytes)
#define SWC_U64   (9*16*12)          // [pos][c][slot12]: k0-4 @0-4, k5-8 @6-9
#define SWE_U64   (9*16*8)           // [k][c][op-pair]
#define SB_U64    10
#define TILE_OFF  ((SWC_U64 + SWE_U64 + SB_U64) * 8)        // 23120 B
#define SMEM_BYTES (TILE_OFF + SH*SW*PSTR*4)                // +66880 = 90000 B

typedef unsigned long long u64;

__device__ float g_pre [N_*64*HW];
__device__ float g_part[N_*4*8*32];

// ---- packed f32x2 helpers ----
__device__ __forceinline__ u64 pack2(float lo, float hi) {
    u64 r; asm("mov.b64 %0,{%1,%2};" : "=l"(r) : "f"(lo), "f"(hi)); return r;
}
__device__ __forceinline__ float2 unpack2(u64 v) {
    float2 r; asm("mov.b64 {%0,%1},%2;" : "=f"(r.x), "=f"(r.y) : "l"(v)); return r;
}
__device__ __forceinline__ void ffma2(u64 &d, u64 a, u64 b) {
    asm("fma.rn.f32x2 %0,%1,%2,%0;" : "+l"(d) : "l"(a), "l"(b));
}
__device__ __forceinline__ u64 mul2(u64 a, u64 b) {
    u64 r; asm("mul.rn.f32x2 %0,%1,%2;" : "=l"(r) : "l"(a), "l"(b)); return r;
}
__device__ __forceinline__ u64 dup2(float v) { return pack2(v, v); }

// One k-chunk: offset conv for taps [KLO,KLO+S) reading smem tile (adjacent-row
// pixel blocking with shared tap loads), then deformable sampling + einsum.
template<int KLO, int S>
__device__ __forceinline__ void chunk(
    u64 acc[PPT][8], const float* __restrict__ tile, const float* __restrict__ xg,
    const u64* __restrict__ swc, const u64* __restrict__ swe,
    const u64* __restrict__ sb,
    int r0loc, int lanex, int ty0, int tx0)
{
    // ---- Phase A: conv accumulation; 4 adjacent pixel rows share tap loads ----
    u64 ao[PPT][S];
    #pragma unroll
    for (int pix = 0; pix < PPT; pix++)
        #pragma unroll
        for (int kk = 0; kk < S; kk++) ao[pix][kk] = sb[KLO + kk];

    #pragma unroll 1
    for (int j = 0; j < 4; j++) {
        #pragma unroll
        for (int cx = 0; cx < 3; cx++) {
            // 6 tap rows cover the 3x3 windows of 4 adjacent pixel rows
            float4 R[6];
            #pragma unroll
            for (int ry = 0; ry < 6; ry++)
                R[ry] = *reinterpret_cast<const float4*>(
                    tile + ((r0loc + HALO - 1 + ry) * SW + (lanex + HALO - 1 + cx)) * PSTR + 4*j);
            #pragma unroll
            for (int posr = 0; posr < 3; posr++) {
                const int pos = posr * 3 + cx;
                #pragma unroll
                for (int q = 0; q < 4; q++) {
                    const u64* wb = swc + (pos * 16 + 4*j + q) * 12;
                    u64 wr[S];
                    if (S == 5) {
                        const ulonglong2 a = *reinterpret_cast<const ulonglong2*>(wb);
                        const ulonglong2 b = *reinterpret_cast<const ulonglong2*>(wb + 2);
                        wr[0] = a.x; wr[1] = a.y; wr[2] = b.x; wr[3] = b.y; wr[4] = wb[4];
                    } else {
                        const ulonglong2 a = *reinterpret_cast<const ulonglong2*>(wb + 6);
                        const ulonglong2 b = *reinterpret_cast<const ulonglong2*>(wb + 8);
                        wr[0] = a.x; wr[1] = a.y; wr[2] = b.x; wr[3] = b.y;
                    }
                    #pragma unroll
                    for (int pix = 0; pix < PPT; pix++) {
                        const float4 X = R[pix + posr];
                        const float xv = (q == 0) ? X.x : (q == 1) ? X.y
                                       : (q == 2) ? X.z : X.w;
                        const u64 xd = dup2(xv);
                        #pragma unroll
                        for (int kk = 0; kk < S; kk++) ffma2(ao[pix][kk], wr[kk], xd);
                    }
                }
            }
        }
    }

    // ---- Phase B: sampling (smem, with rare global fallback) + einsum ----
    const int oy = ty0 - HALO, ox = tx0 - HALO;
    #pragma unroll 1
    for (int kk = 0; kk < S; kk++) {
        const int k = KLO + kk;
        const int kdy = k / 3 - 1, kdx = k % 3 - 1;
        u64 wwd[PPT][4];
        int cw[PPT][4];
        bool inw[PPT];
        #pragma unroll
        for (int pix = 0; pix < PPT; pix++) {
            const float2 off = unpack2(ao[pix][kk]);
            const int hg = ty0 + r0loc + pix;
            const int wg = tx0 + lanex;
            const float py = (float)(hg + kdy) + off.x;
            const float px = (float)(wg + kdx) + off.y;
            const float y0f = floorf(py), x0f = floorf(px);
            const float fy = py - y0f, fx = px - x0f;
            const int y0 = (int)y0f, x0 = (int)x0f;
            const bool vy0 = (y0 >= 0)  && (y0 < 64);
            const bool vy1 = (y0 >= -1) && (y0 < 63);
            const bool vx0 = (x0 >= 0)  && (x0 < 64);
            const bool vx1 = (x0 >= -1) && (x0 < 63);
            wwd[pix][0] = dup2((1.f - fy) * (1.f - fx) * ((vy0 && vx0) ? 1.f : 0.f));
            wwd[pix][1] = dup2((1.f - fy) * fx         * ((vy0 && vx1) ? 1.f : 0.f));
            wwd[pix][2] = dup2(fy * (1.f - fx)         * ((vy1 && vx0) ? 1.f : 0.f));
            wwd[pix][3] = dup2(fy * fx                 * ((vy1 && vx1) ? 1.f : 0.f));
            const int yc0 = min(max(y0, 0), 63), yc1 = min(max(y0 + 1, 0), 63);
            const int xc0 = min(max(x0, 0), 63), xc1 = min(max(x0 + 1, 0), 63);
            const int t0y = yc0 - oy, t1y = yc1 - oy;
            const int t0x = xc0 - ox, t1x = xc1 - ox;
            const bool win = (t0y >= 0) && (t1y < SH) && (t0x >= 0) && (t1x < SW);
            inw[pix] = win;
            if (win) {
                cw[pix][0] = (t0y * SW + t0x) * PSTR; cw[pix][1] = (t0y * SW + t1x) * PSTR;
                cw[pix][2] = (t1y * SW + t0x) * PSTR; cw[pix][3] = (t1y * SW + t1x) * PSTR;
            } else {   // global pixel indices (rare path)
                cw[pix][0] = yc0 * 64 + xc0; cw[pix][1] = yc0 * 64 + xc1;
                cw[pix][2] = yc1 * 64 + xc0; cw[pix][3] = yc1 * 64 + xc1;
            }
        }
        const u64* web = swe + (k * 16) * 8;
        #pragma unroll
        for (int j = 0; j < 4; j++) {
            u64 vd[PPT][4];
            #pragma unroll
            for (int pix = 0; pix < PPT; pix++) {
                ulonglong2 A2, B2, C2, D2;
                if (inw[pix]) {
                    A2 = *reinterpret_cast<const ulonglong2*>(tile + cw[pix][0] + 4*j);
                    B2 = *reinterpret_cast<const ulonglong2*>(tile + cw[pix][1] + 4*j);
                    C2 = *reinterpret_cast<const ulonglong2*>(tile + cw[pix][2] + 4*j);
                    D2 = *reinterpret_cast<const ulonglong2*>(tile + cw[pix][3] + 4*j);
                } else {
                    const float* xq = xg + (size_t)(4*j) * HW;
                    const int i0 = cw[pix][0], i1 = cw[pix][1], i2 = cw[pix][2], i3 = cw[pix][3];
                    A2.x = pack2(xq[i0], xq[HW + i0]); A2.y = pack2(xq[2*HW + i0], xq[3*HW + i0]);
                    B2.x = pack2(xq[i1], xq[HW + i1]); B2.y = pack2(xq[2*HW + i1], xq[3*HW + i1]);
                    C2.x = pack2(xq[i2], xq[HW + i2]); C2.y = pack2(xq[2*HW + i2], xq[3*HW + i2]);
                    D2.x = pack2(xq[i3], xq[HW + i3]); D2.y = pack2(xq[2*HW + i3], xq[3*HW + i3]);
                }
                u64 v01 = mul2(wwd[pix][0], A2.x);
                ffma2(v01, wwd[pix][1], B2.x);
                ffma2(v01, wwd[pix][2], C2.x);
                ffma2(v01, wwd[pix][3], D2.x);
                u64 v23 = mul2(wwd[pix][0], A2.y);
                ffma2(v23, wwd[pix][1], B2.y);
                ffma2(v23, wwd[pix][2], C2.y);
                ffma2(v23, wwd[pix][3], D2.y);
                const float2 t01 = unpack2(v01), t23 = unpack2(v23);
                vd[pix][0] = dup2(t01.x); vd[pix][1] = dup2(t01.y);
                vd[pix][2] = dup2(t23.x); vd[pix][3] = dup2(t23.y);
            }
            #pragma unroll
            for (int q = 0; q < 4; q++) {
                const ulonglong2* we2 =
                    reinterpret_cast<const ulonglong2*>(web + (4*j + q) * 8);
                const ulonglong2 e0 = we2[0], e1 = we2[1], e2 = we2[2], e3 = we2[3];
                #pragma unroll
                for (int pix = 0; pix < PPT; pix++) {
                    const u64 v = vd[pix][q];
                    ffma2(acc[pix][0], e0.x, v); ffma2(acc[pix][1], e0.y, v);
                    ffma2(acc[pix][2], e1.x, v); ffma2(acc[pix][3], e1.y, v);
                    ffma2(acc[pix][4], e2.x, v); ffma2(acc[pix][5], e2.y, v);
                    ffma2(acc[pix][6], e3.x, v); ffma2(acc[pix][7], e3.y, v);
                }
            }
        }
    }
}

__global__ __launch_bounds__(THREADS) void fused_kernel(const float* __restrict__ x,
                                                        const float* __restrict__ w_off,
                                                        const float* __restrict__ b_off,
                                                        const float* __restrict__ w_dc) {
    extern __shared__ __align__(16) char smem_raw[];
    u64*   swc  = reinterpret_cast<u64*>(smem_raw);
    u64*   swe  = swc + SWC_U64;
    u64*   sb   = swe + SWE_U64;
    float* tile = reinterpret_cast<float*>(smem_raw + TILE_OFF);
    __shared__ float s_red[4][32];

    const int tid = threadIdx.x;
    const int bx = blockIdx.x, g = blockIdx.y, n = blockIdx.z;
    const int ty0 = (bx >> 2) * TH, tx0 = (bx & 3) * TW;
    const float* xg = x + ((size_t)(n * 64 + g * 16)) * HW;

    // Pack weights into smem (paired for f32x2)
    for (int i = tid; i < SWC_U64; i += THREADS) {
        const int slot = i % 12, c = (i / 12) % 16, pos = i / 192;
        int k = -1;
        if (slot < 5) k = slot;
        else if (slot >= 6 && slot <= 9) k = slot - 1;
        u64 v = 0ULL;
        if (k >= 0)
            v = pack2(w_off[((g*18 + 2*k)   * 16 + c) * 9 + pos],
                      w_off[((g*18 + 2*k+1) * 16 + c) * 9 + pos]);
        swc[i] = v;
    }
    for (int i = tid; i < SWE_U64; i += THREADS) {
        const int op = i % 8, c = (i / 8) % 16, k = i / 128;
        swe[i] = pack2(w_dc[((g*16 + 2*op)   * 16 + c) * 9 + k],
                       w_dc[((g*16 + 2*op+1) * 16 + c) * 9 + k]);
    }
    if (tid < SB_U64)
        sb[tid] = (tid < 9) ? pack2(b_off[g*18 + 2*tid], b_off[g*18 + 2*tid + 1]) : 0ULL;

    // Fill tile (zero halo outside image = conv boundary skip)
    for (int sp = tid; sp < SH * SW; sp += THREADS) {
        const int gy = ty0 - HALO + sp / SW;
        const int gx = tx0 - HALO + sp % SW;
        const bool in = ((unsigned)gy < 64u) && ((unsigned)gx < 64u);
        const int gp = gy * 64 + gx;
        #pragma unroll
        for (int c = 0; c < 16; c++)
            tile[sp * PSTR + c] = in ? xg[(size_t)c * HW + gp] : 0.f;
    }
    __syncthreads();

    const int r0loc = (tid >> 4) * PPT;     // 4 ADJACENT pixel rows per thread
    const int lanex = tid & 15;

    u64 acc[PPT][8];
    #pragma unroll
    for (int pix = 0; pix < PPT; pix++)
        #pragma unroll
        for (int op = 0; op < 8; op++) acc[pix][op] = 0ULL;

    chunk<0, 5>(acc, tile, xg, swc, swe, sb, r0loc, lanex, ty0, tx0);
    chunk<5, 4>(acc, tile, xg, swc, swe, sb, r0loc, lanex, ty0, tx0);

    // ---- write pre-norm output + block-local stats ----
    float sv[16], sq[16];
    #pragma unroll
    for (int o = 0; o < 16; o++) { sv[o] = 0.f; sq[o] = 0.f; }
    #pragma unroll
    for (int pix = 0; pix < PPT; pix++) {
        const int p0 = (ty0 + r0loc + pix) * 64 + tx0 + lanex;
        float* pre = g_pre + ((size_t)(n * 64 + g * 16)) * HW + p0;
        #pragma unroll
        for (int op = 0; op < 8; op++) {
            const float2 t = unpack2(acc[pix][op]);
            pre[(size_t)(2*op)     * HW] = t.x;
            pre[(size_t)(2*op + 1) * HW] = t.y;
            sv[2*op]     += t.x; sq[2*op]     += t.x * t.x;
            sv[2*op + 1] += t.y; sq[2*op + 1] += t.y * t.y;
        }
    }
    const int wi = tid >> 5, lane = tid & 31;
    #pragma unroll
    for (int o = 0; o < 16; o++) {
        #pragma unroll
        for (int d = 16; d; d >>= 1) {
            sv[o] += __shfl_xor_sync(0xffffffffu, sv[o], d);
            sq[o] += __shfl_xor_sync(0xffffffffu, sq[o], d);
        }
    }
    if (lane == 0) {
        #pragma unroll
        for (int o = 0; o < 16; o++) { s_red[wi][o] = sv[o]; s_red[wi][16 + o] = sq[o]; }
    }
    __syncthreads();
    if (tid < 32) {
        const float v = s_red[0][tid] + s_red[1][tid] + s_red[2][tid] + s_red[3][tid];
        g_part[(((n * 4 + g) * 8) + bx) * 32 + tid] = v;
    }
}

// Normalize + exact GELU + transposed store
__global__ void norm_gelu_kernel(float* __restrict__ out) {
    const int oc = blockIdx.y;
    const int n  = blockIdx.z;
    const int g = oc >> 4, o = oc & 15;

    float s = 0.f, q = 0.f;
    #pragma unroll
    for (int b = 0; b < 8; b++) {
        const float* pp = g_part + ((n * 4 + g) * 8 + b) * 32;
        s += pp[o]; q += pp[16 + o];
    }
    const float mean = s * (1.f / HW);
    const float var  = q * (1.f / HW) - mean * mean;
    const float inv  = rsqrtf(var + 1e-5f);

    const int p4 = blockIdx.x * blockDim.x + threadIdx.x;
    const float4 v = reinterpret_cast<const float4*>(g_pre + ((size_t)(n * 64 + oc)) * HW)[p4];
    float4 r;
    { const float a = (v.x - mean) * inv; r.x = 0.5f * a * (1.f + erff(a * 0.7071067811865475f)); }
    { const float a = (v.y - mean) * inv; r.y = 0.5f * a * (1.f + erff(a * 0.7071067811865475f)); }
    { const float a = (v.z - mean) * inv; r.z = 0.5f * a * (1.f + erff(a * 0.7071067811865475f)); }
    { const float a = (v.w - mean) * inv; r.w = 0.5f * a * (1.f + erff(a * 0.7071067811865475f)); }

    const int b = n >> 3, d = n & 7;
    reinterpret_cast<float4*>(out + ((size_t)((b * 64 + oc) * 8 + d)) * HW)[p4] = r;
}

extern "C" void kernel_launch(void* const* d_in, const int* in_sizes, int n_in,
                              void* d_out, int out_size) {
    const float* x     = (const float*)d_in[0];
    const float* w_off = (const float*)d_in[1];
    const float* b_off = (const float*)d_in[2];
    const float* w_dc  = (const float*)d_in[3];
    // d_in[4] = b_dc: cancels exactly under per-channel mean subtraction.
    float* out = (float*)d_out;

    cudaFuncSetAttribute(fused_kernel,
                         cudaFuncAttributeMaxDynamicSharedMemorySize, SMEM_BYTES);

    fused_kernel<<<dim3(8, G_, N_), THREADS, SMEM_BYTES>>>(x, w_off, b_off, w_dc);
    norm_gelu_kernel<<<dim3(HW / 1024, 64, N_), 256>>>(out);
}